// round 1
// baseline (speedup 1.0000x reference)
#include <cuda_runtime.h>
#include <math.h>

#define N_NODES 20000
#define N_EDGES 640000
#define ETILE 32
#define EDGE_THREADS 256

// Scratch (allocation-free rule: __device__ globals)
__device__ float g_y[N_NODES * 80];      // 6.4 MB  (y = l1-transformed node features, gather source)
__device__ float g_agg[N_NODES * 192];   // 15.36 MB (segment-sum accumulator)

// ---------------------------------------------------------------------------
// Zero the accumulator
// ---------------------------------------------------------------------------
__global__ void zero_agg_kernel() {
    int i = blockIdx.x * blockDim.x + threadIdx.x;
    if (i < N_NODES * 192 / 4)
        ((float4*)g_agg)[i] = make_float4(0.f, 0.f, 0.f, 0.f);
}

// ---------------------------------------------------------------------------
// Node transform: out = c_s * s (self-connection part), g_y = y (l1 part)
// ---------------------------------------------------------------------------
__global__ void node_kernel(const float* __restrict__ node_input,
                            const float* __restrict__ node_attr,
                            const float* __restrict__ Wsc0,
                            const float* __restrict__ Wsc1,
                            const float* __restrict__ Wl10,
                            const float* __restrict__ Wl11,
                            float* __restrict__ out) {
    __shared__ float s0[32 * 32], l0[32 * 32], s1[16 * 16], l1[16 * 16];
    for (int i = threadIdx.x; i < 1024; i += blockDim.x) { s0[i] = Wsc0[i]; l0[i] = Wl10[i]; }
    for (int i = threadIdx.x; i < 256;  i += blockDim.x) { s1[i] = Wsc1[i]; l1[i] = Wl11[i]; }
    __syncthreads();

    int idx = blockIdx.x * blockDim.x + threadIdx.x;
    if (idx >= N_NODES * 80) return;
    int n = idx / 80, j = idx - n * 80;
    const float* x = node_input + n * 80;
    float a = node_attr[n];
    const float c_s = 0.3826834323650898f;   // sin(pi/8)

    float acc_s = 0.f, acc_l = 0.f;
    if (j < 32) {
#pragma unroll
        for (int u = 0; u < 32; u++) {
            float xv = x[u];
            acc_s += xv * s0[u * 32 + j];
            acc_l += xv * l0[u * 32 + j];
        }
        const float inv = 0.17677669529663687f;  // 1/sqrt(32)
        out[idx] = c_s * acc_s * inv * a;
        g_y[idx] = acc_l * inv * a;
    } else {
        int g = j - 32, v = g / 3, i3 = g - v * 3;
#pragma unroll
        for (int u = 0; u < 16; u++) {
            float xv = x[32 + u * 3 + i3];
            acc_s += xv * s1[u * 16 + v];
            acc_l += xv * l1[u * 16 + v];
        }
        out[idx] = c_s * acc_s * 0.25f * a;      // 1/sqrt(16)
        g_y[idx] = acc_l * 0.25f * a;
    }
}

// ---------------------------------------------------------------------------
// Fused edge kernel: MLP(10->64->96) + tensor-product message + atomic scatter
// Persistent blocks, 32 edges per tile, 256 threads (8 threads per edge).
// Dynamic smem layout (floats):
//   sW1[6144] sW0[640] sES[320] sEA[128] sH[32*65] sWo[32*96] sY[32*80] sSrc/sDst[64 ints]
// ---------------------------------------------------------------------------
__global__ void __launch_bounds__(EDGE_THREADS)
edge_kernel(const float* __restrict__ edge_attr,
            const float* __restrict__ edge_scalars,
            const float* __restrict__ Wfc0,
            const float* __restrict__ Wfc1,
            const int* __restrict__ edge_index,
            int ntiles) {
    extern __shared__ float sm[];
    float* sW1 = sm;                // 6144   (pre-scaled)
    float* sW0 = sW1 + 6144;        // 640    (pre-scaled by 1/sqrt(10))
    float* sES = sW0 + 640;         // 320
    float* sEA = sES + 320;         // 128
    float* sH  = sEA + 128;         // 2080   (stride 65 to avoid bank conflicts)
    float* sWo = sH + 2080;         // 3072
    float* sY  = sWo + 3072;        // 2560
    int*   sSrc = (int*)(sY + 2560);
    int*   sDst = sSrc + ETILE;

    const int tid = threadIdx.x;

    // Fold 1/sqrt(64) * 1/sqrt(NUM_NEIGHBORS=32) into W_fc1; extra 1/sqrt(3)
    // on the w_d columns (80..95).
    const float w1scale = 0.02209708691207961f;       // 1/(8*sqrt(32))
    const float invs3   = 0.5773502691896258f;        // 1/sqrt(3)
    for (int i = tid; i < 6144; i += EDGE_THREADS) {
        int col = i % 96;
        float s = w1scale * ((col >= 80) ? invs3 : 1.0f);
        sW1[i] = Wfc1[i] * s;
    }
    const float invs10 = 0.31622776601683794f;        // 1/sqrt(10)
    for (int i = tid; i < 640; i += EDGE_THREADS) sW0[i] = Wfc0[i] * invs10;
    __syncthreads();

    const int e_id = tid >> 3;   // 0..31  (edge within tile)
    const int sub  = tid & 7;    // 0..7   (worker within edge)

    for (int tile = blockIdx.x; tile < ntiles; tile += gridDim.x) {
        int e0 = tile * ETILE;
        int cnt = N_EDGES - e0; if (cnt > ETILE) cnt = ETILE;

        for (int i = tid; i < cnt * 10; i += EDGE_THREADS) sES[i] = edge_scalars[e0 * 10 + i];
        for (int i = tid; i < cnt * 4;  i += EDGE_THREADS) sEA[i] = edge_attr[e0 * 4 + i];
        if (tid < cnt) {
            sSrc[tid] = edge_index[e0 + tid];
            sDst[tid] = edge_index[N_EDGES + e0 + tid];
        }
        __syncthreads();

        // gather y[src] rows: 20 float4 per edge
        for (int i = tid; i < cnt * 20; i += EDGE_THREADS) {
            int e = i / 20, c = i - e * 20;
            ((float4*)sY)[e * 20 + c] = ((const float4*)(g_y + sSrc[e] * 80))[c];
        }
        __syncthreads();

        // ---- layer 1: h = silu(es @ W0) ; 8 outputs per thread ----
        if (e_id < cnt) {
            float es[10];
#pragma unroll
            for (int k = 0; k < 10; k++) es[k] = sES[e_id * 10 + k];
            float acc[8];
#pragma unroll
            for (int j = 0; j < 8; j++) acc[j] = 0.f;
            int c0 = sub * 8;
#pragma unroll
            for (int k = 0; k < 10; k++) {
                float x = es[k];
#pragma unroll
                for (int j = 0; j < 8; j++) acc[j] += x * sW0[k * 64 + c0 + j];
            }
#pragma unroll
            for (int j = 0; j < 8; j++) {
                float aa = acc[j];
                sH[e_id * 65 + c0 + j] = aa / (1.0f + __expf(-aa));
            }
        }
        __syncthreads();

        // ---- layer 2: w = h @ W1 ; 12 outputs per thread ----
        if (e_id < cnt) {
            float acc[12];
#pragma unroll
            for (int j = 0; j < 12; j++) acc[j] = 0.f;
            int c0 = sub * 12;
#pragma unroll 8
            for (int k = 0; k < 64; k++) {
                float hk = sH[e_id * 65 + k];
#pragma unroll
                for (int j = 0; j < 12; j++) acc[j] += hk * sW1[k * 96 + c0 + j];
            }
#pragma unroll
            for (int j = 0; j < 12; j++) sWo[e_id * 96 + c0 + j] = acc[j];
        }
        __syncthreads();

        // ---- message + scatter: 24 outputs (6 vec4) per thread ----
        if (e_id < cnt) {
            const float* we = sWo + e_id * 96;
            const float* ye = sY + e_id * 80;
            float ea0 = sEA[e_id * 4 + 0];
            float e1x = sEA[e_id * 4 + 1];
            float e1y = sEA[e_id * 4 + 2];
            float e1z = sEA[e_id * 4 + 3];
            float* aggb = g_agg + (long long)sDst[e_id] * 192;
            int f0 = sub * 24;
#pragma unroll
            for (int f4 = 0; f4 < 6; f4++) {
                float v[4];
#pragma unroll
                for (int q = 0; q < 4; q++) {
                    int f = f0 + f4 * 4 + q;
                    float val;
                    if (f < 32) {                                   // m_a
                        val = we[f] * ye[f] * ea0;
                    } else if (f < 48) {                            // m_d (1/sqrt3 folded into w)
                        int u = f - 32;
                        const float* x1 = ye + 32 + u * 3;
                        val = we[80 + u] * (x1[0] * e1x + x1[1] * e1y + x1[2] * e1z);
                    } else if (f < 144) {                           // m_b
                        int g = f - 48; int c = g / 3, i = g - c * 3;
                        float e1v = (i == 0) ? e1x : ((i == 1) ? e1y : e1z);
                        val = we[32 + c] * ye[c] * e1v;
                    } else {                                        // m_c
                        int g = f - 144; int u = g / 3, i = g - u * 3;
                        float e1v = (i == 0) ? e1x : ((i == 1) ? e1y : e1z);
                        val = we[64 + u] * ye[32 + u * 3 + i] * ea0;
                    }
                    v[q] = val;
                }
                float* p = aggb + f0 + f4 * 4;
                asm volatile("red.global.add.v4.f32 [%0], {%1,%2,%3,%4};"
                             :: "l"(p), "f"(v[0]), "f"(v[1]), "f"(v[2]), "f"(v[3])
                             : "memory");
            }
        }
        __syncthreads();
    }
}

// ---------------------------------------------------------------------------
// Final: out += c_x * (agg @ W_l2) / sqrt(48)
// ---------------------------------------------------------------------------
__global__ void final_kernel(const float* __restrict__ Wl20,
                             const float* __restrict__ Wl21,
                             float* __restrict__ out) {
    __shared__ float sW0[48 * 32];
    __shared__ float sW1[48 * 16];
    const float sc = 0.9238795325112867f * 0.14433756729740643f;  // cos(pi/8)/sqrt(48)
    for (int i = threadIdx.x; i < 48 * 32; i += blockDim.x) sW0[i] = Wl20[i] * sc;
    for (int i = threadIdx.x; i < 48 * 16; i += blockDim.x) sW1[i] = Wl21[i] * sc;
    __syncthreads();

    int idx = blockIdx.x * blockDim.x + threadIdx.x;
    if (idx >= N_NODES * 80) return;
    int n = idx / 80, j = idx - n * 80;
    const float* a = g_agg + (long long)n * 192;
    float z = 0.f;
    if (j < 32) {
#pragma unroll
        for (int u = 0; u < 48; u++) z += a[u] * sW0[u * 32 + j];
    } else {
        int g = j - 32, v = g / 3, i3 = g - v * 3;
        const float* a1 = a + 48;
#pragma unroll
        for (int u = 0; u < 48; u++) z += a1[u * 3 + i3] * sW1[u * 16 + v];
    }
    out[idx] += z;
}

// ---------------------------------------------------------------------------
extern "C" void kernel_launch(void* const* d_in, const int* in_sizes, int n_in,
                              void* d_out, int out_size) {
    const float* node_input   = (const float*)d_in[0];
    const float* node_attr    = (const float*)d_in[1];
    const float* edge_attr    = (const float*)d_in[2];
    const float* edge_scalars = (const float*)d_in[3];
    const float* Wsc0 = (const float*)d_in[4];
    const float* Wsc1 = (const float*)d_in[5];
    const float* Wl10 = (const float*)d_in[6];
    const float* Wl11 = (const float*)d_in[7];
    const float* Wfc0 = (const float*)d_in[8];
    const float* Wfc1 = (const float*)d_in[9];
    const float* Wl20 = (const float*)d_in[10];
    const float* Wl21 = (const float*)d_in[11];
    const int*   edge_index = (const int*)d_in[12];
    float* out = (float*)d_out;

    // dynamic smem: 14944 floats + 64 ints = 60032 bytes
    const int smem_bytes = (6144 + 640 + 320 + 128 + 2080 + 3072 + 2560) * 4 + 64 * 4;
    cudaFuncSetAttribute(edge_kernel, cudaFuncAttributeMaxDynamicSharedMemorySize, smem_bytes);

    zero_agg_kernel<<<(N_NODES * 192 / 4 + 255) / 256, 256>>>();
    node_kernel<<<(N_NODES * 80 + 255) / 256, 256>>>(node_input, node_attr,
                                                     Wsc0, Wsc1, Wl10, Wl11, out);
    int ntiles = (N_EDGES + ETILE - 1) / ETILE;
    edge_kernel<<<1184, EDGE_THREADS, smem_bytes>>>(edge_attr, edge_scalars,
                                                    Wfc0, Wfc1, edge_index, ntiles);
    final_kernel<<<(N_NODES * 80 + 255) / 256, 256>>>(Wl20, Wl21, out);
}

// round 3
// speedup vs baseline: 1.4302x; 1.4302x over previous
#include <cuda_runtime.h>
#include <math.h>

#define N_NODES 20000
#define N_EDGES 640000

// Scratch (allocation-free rule: __device__ globals)
__device__ float g_y[N_NODES * 80];       // 6.4 MB  l1-transformed node features
__device__ float g_agg[N_NODES * 192];    // 15.36 MB segment-sum accumulator
__device__ float g_w[N_EDGES * 96];       // 245.8 MB per-edge MLP outputs (pre-scaled)

// ---------------------------------------------------------------------------
// f32x2 packed helpers (sm_100+): FFMA2 doubles fp32 FMA throughput.
// ---------------------------------------------------------------------------
__device__ __forceinline__ unsigned long long pack2(float x) {
    unsigned long long r;
    asm("mov.b64 %0, {%1, %1};" : "=l"(r) : "f"(x));
    return r;
}
__device__ __forceinline__ void ffma2(unsigned long long& d,
                                      unsigned long long a,
                                      unsigned long long b) {
    asm("fma.rn.f32x2 %0, %1, %2, %0;" : "+l"(d) : "l"(a), "l"(b));
}

// ---------------------------------------------------------------------------
__global__ void zero_agg_kernel() {
    int i = blockIdx.x * blockDim.x + threadIdx.x;
    if (i < N_NODES * 192 / 4)
        ((float4*)g_agg)[i] = make_float4(0.f, 0.f, 0.f, 0.f);
}

// ---------------------------------------------------------------------------
// Node transform: out = c_s * s, g_y = y.  16 nodes per 256-thread block;
// node rows staged through smem (coalesced float4) to kill stride-3 LDGs.
// ---------------------------------------------------------------------------
__global__ void __launch_bounds__(256) node_kernel(
        const float* __restrict__ node_input,
        const float* __restrict__ node_attr,
        const float* __restrict__ Wsc0, const float* __restrict__ Wsc1,
        const float* __restrict__ Wl10, const float* __restrict__ Wl11,
        float* __restrict__ out) {
    __shared__ float s0[32 * 32], l0[32 * 32], s1[16 * 16], l1[16 * 16];
    __shared__ float sx[16 * 80];
    __shared__ float sa[16];
    for (int i = threadIdx.x; i < 1024; i += 256) { s0[i] = Wsc0[i]; l0[i] = Wl10[i]; }
    for (int i = threadIdx.x; i < 256;  i += 256) { s1[i] = Wsc1[i]; l1[i] = Wl11[i]; }

    int n0 = blockIdx.x * 16;
    int nodes = N_NODES - n0; if (nodes > 16) nodes = 16;
    for (int i = threadIdx.x; i < nodes * 20; i += 256)
        ((float4*)sx)[i] = ((const float4*)(node_input + (long long)n0 * 80))[i];
    if (threadIdx.x < nodes) sa[threadIdx.x] = node_attr[n0 + threadIdx.x];
    __syncthreads();

    int ln = threadIdx.x >> 4;      // local node 0..15
    int q  = threadIdx.x & 15;      // 5 outputs each
    if (ln >= nodes) return;
    const float* x = sx + ln * 80;
    float a = sa[ln];
    const float c_s = 0.3826834323650898f;   // sin(pi/8)
    float* outr = out + (long long)(n0 + ln) * 80;
    float* yr   = g_y + (long long)(n0 + ln) * 80;

#pragma unroll
    for (int t = 0; t < 5; t++) {
        int j = q * 5 + t;
        float acc_s = 0.f, acc_l = 0.f;
        if (j < 32) {
#pragma unroll
            for (int u = 0; u < 32; u++) {
                float xv = x[u];
                acc_s += xv * s0[u * 32 + j];
                acc_l += xv * l0[u * 32 + j];
            }
            const float inv = 0.17677669529663687f;  // 1/sqrt(32)
            outr[j] = c_s * acc_s * inv * a;
            yr[j]   = acc_l * inv * a;
        } else {
            int g = j - 32, v = g / 3, i3 = g - v * 3;
#pragma unroll
            for (int u = 0; u < 16; u++) {
                float xv = x[32 + u * 3 + i3];
                acc_s += xv * s1[u * 16 + v];
                acc_l += xv * l1[u * 16 + v];
            }
            outr[j] = c_s * acc_s * 0.25f * a;       // 1/sqrt(16)
            yr[j]   = acc_l * 0.25f * a;
        }
    }
}

// ---------------------------------------------------------------------------
// Edge MLP: 128 edges/CTA, 256 threads. Layer1 scalar (tiny), layer2 with
// packed f32x2 FMAs, h tile transposed in smem so 4 edges load as LDS.128.
// Writes pre-scaled w (incl. 1/sqrt(64), 1/sqrt(32), 1/sqrt(3) on w_d cols).
// ---------------------------------------------------------------------------
#define MTILE 128
__global__ void __launch_bounds__(256) mlp_kernel(
        const float* __restrict__ edge_scalars,
        const float* __restrict__ Wfc0,
        const float* __restrict__ Wfc1) {
    __shared__ float sW0[10 * 64];
    __shared__ float sW1[64 * 96];
    __shared__ float sES[MTILE * 10];
    __shared__ float sHT[64 * 132];     // transposed h, padded for LDS.128 alignment

    const int tid = threadIdx.x;
    const int e0 = blockIdx.x * MTILE;

    const float invs10 = 0.31622776601683794f;        // 1/sqrt(10)
    for (int i = tid; i < 640; i += 256) sW0[i] = Wfc0[i] * invs10;
    const float w1scale = 0.02209708691207961f;       // 1/(8*sqrt(32))
    const float invs3   = 0.5773502691896258f;        // 1/sqrt(3)
    for (int i = tid; i < 6144; i += 256) {
        int col = i % 96;
        sW1[i] = Wfc1[i] * (col >= 80 ? w1scale * invs3 : w1scale);
    }
    for (int i = tid; i < MTILE * 10; i += 256) sES[i] = edge_scalars[e0 * 10 + i];
    __syncthreads();

    // ---- layer 1: 2 threads per edge, 32 h-cols each ----
    {
        int e  = tid >> 1;
        int c0 = (tid & 1) * 32;
        float es[10];
#pragma unroll
        for (int k = 0; k < 10; k++) es[k] = sES[e * 10 + k];
        float acc[32];
#pragma unroll
        for (int j = 0; j < 32; j++) acc[j] = 0.f;
#pragma unroll
        for (int k = 0; k < 10; k++) {
            float x = es[k];
#pragma unroll
            for (int j = 0; j < 32; j++) acc[j] += x * sW0[k * 64 + c0 + j];
        }
#pragma unroll
        for (int j = 0; j < 32; j++) {
            float aa = acc[j];
            sHT[(c0 + j) * 132 + e] = aa / (1.0f + __expf(-aa));
        }
    }
    __syncthreads();

    // ---- layer 2: thread = 4 edges x 12 cols (6 f32x2 col-pairs) ----
    {
        int eb = (tid >> 3) * 4;     // edge base (0..124)
        int c0 = (tid & 7) * 12;     // col base  (0..84)
        unsigned long long acc[4][6];
#pragma unroll
        for (int e = 0; e < 4; e++)
#pragma unroll
            for (int p = 0; p < 6; p++) acc[e][p] = 0ull;

#pragma unroll 4
        for (int k = 0; k < 64; k++) {
            float4 h4 = *(const float4*)&sHT[k * 132 + eb];
            unsigned long long hp0 = pack2(h4.x);
            unsigned long long hp1 = pack2(h4.y);
            unsigned long long hp2 = pack2(h4.z);
            unsigned long long hp3 = pack2(h4.w);
            const float* wr = &sW1[k * 96 + c0];
#pragma unroll
            for (int p = 0; p < 6; p++) {
                unsigned long long wp = *(const unsigned long long*)&wr[2 * p];
                ffma2(acc[0][p], hp0, wp);
                ffma2(acc[1][p], hp1, wp);
                ffma2(acc[2][p], hp2, wp);
                ffma2(acc[3][p], hp3, wp);
            }
        }
#pragma unroll
        for (int e = 0; e < 4; e++) {
            float* dst = g_w + (long long)(e0 + eb + e) * 96 + c0;
#pragma unroll
            for (int pp = 0; pp < 3; pp++) {
                ulonglong2 v;
                v.x = acc[e][2 * pp];
                v.y = acc[e][2 * pp + 1];
                *(ulonglong2*)(dst + 4 * pp) = v;
            }
        }
    }
}

// ---------------------------------------------------------------------------
// Message + scatter: 64 edges/CTA, 512 threads (8 subs/edge, 24 fields each).
// ---------------------------------------------------------------------------
#define ETILE 64
__global__ void __launch_bounds__(512) msg_kernel(
        const float* __restrict__ edge_attr,
        const int* __restrict__ edge_index) {
    __shared__ float sw[ETILE * 96];
    __shared__ float sy[ETILE * 80];
    __shared__ float sea[ETILE * 4];
    __shared__ int ssrc[ETILE], sdst[ETILE];

    const int tid = threadIdx.x;
    const int e0 = blockIdx.x * ETILE;

    for (int i = tid; i < ETILE * 24; i += 512)
        ((float4*)sw)[i] = ((const float4*)(g_w + (long long)e0 * 96))[i];
    for (int i = tid; i < ETILE * 4; i += 512) sea[i] = edge_attr[e0 * 4 + i];
    if (tid < ETILE) {
        ssrc[tid] = edge_index[e0 + tid];
        sdst[tid] = edge_index[N_EDGES + e0 + tid];
    }
    __syncthreads();

    for (int i = tid; i < ETILE * 20; i += 512) {
        int e = i / 20, c = i - e * 20;
        ((float4*)sy)[e * 20 + c] = ((const float4*)(g_y + (long long)ssrc[e] * 80))[c];
    }
    __syncthreads();

    const int e_id = tid >> 3;   // 0..63
    const int sub  = tid & 7;    // 0..7
    const float* we = sw + e_id * 96;
    const float* ye = sy + e_id * 80;
    float ea0 = sea[e_id * 4 + 0];
    float e1x = sea[e_id * 4 + 1];
    float e1y = sea[e_id * 4 + 2];
    float e1z = sea[e_id * 4 + 3];
    float* aggb = g_agg + (long long)sdst[e_id] * 192;
    int f0 = sub * 24;
#pragma unroll
    for (int f4 = 0; f4 < 6; f4++) {
        float v[4];
#pragma unroll
        for (int q = 0; q < 4; q++) {
            int f = f0 + f4 * 4 + q;
            float val;
            if (f < 32) {                                   // m_a
                val = we[f] * ye[f] * ea0;
            } else if (f < 48) {                            // m_d (1/sqrt3 folded into w)
                int u = f - 32;
                const float* x1 = ye + 32 + u * 3;
                val = we[80 + u] * (x1[0] * e1x + x1[1] * e1y + x1[2] * e1z);
            } else if (f < 144) {                           // m_b
                int g = f - 48; int c = g / 3, i = g - c * 3;
                float e1v = (i == 0) ? e1x : ((i == 1) ? e1y : e1z);
                val = we[32 + c] * ye[c] * e1v;
            } else {                                        // m_c
                int g = f - 144; int u = g / 3, i = g - u * 3;
                float e1v = (i == 0) ? e1x : ((i == 1) ? e1y : e1z);
                val = we[64 + u] * ye[32 + u * 3 + i] * ea0;
            }
            v[q] = val;
        }
        float* p = aggb + f0 + f4 * 4;
        asm volatile("red.global.add.v4.f32 [%0], {%1,%2,%3,%4};"
                     :: "l"(p), "f"(v[0]), "f"(v[1]), "f"(v[2]), "f"(v[3])
                     : "memory");
    }
}

// ---------------------------------------------------------------------------
// Final: out += c_x * (agg @ W_l2) / sqrt(48).  16 nodes per 256-thread block,
// agg rows staged through smem.
// ---------------------------------------------------------------------------
__global__ void __launch_bounds__(256) final_kernel(
        const float* __restrict__ Wl20,
        const float* __restrict__ Wl21,
        float* __restrict__ out) {
    __shared__ float sW0[48 * 32];
    __shared__ float sW1[48 * 16];
    __shared__ float sa[16 * 192];
    const float sc = 0.9238795325112867f * 0.14433756729740643f;  // cos(pi/8)/sqrt(48)
    for (int i = threadIdx.x; i < 48 * 32; i += 256) sW0[i] = Wl20[i] * sc;
    for (int i = threadIdx.x; i < 48 * 16; i += 256) sW1[i] = Wl21[i] * sc;

    int n0 = blockIdx.x * 16;
    int nodes = N_NODES - n0; if (nodes > 16) nodes = 16;
    for (int i = threadIdx.x; i < nodes * 48; i += 256)
        ((float4*)sa)[i] = ((const float4*)(g_agg + (long long)n0 * 192))[i];
    __syncthreads();

    int ln = threadIdx.x >> 4;
    int q  = threadIdx.x & 15;
    if (ln >= nodes) return;
    const float* a = sa + ln * 192;
    float* outr = out + (long long)(n0 + ln) * 80;

#pragma unroll
    for (int t = 0; t < 5; t++) {
        int j = q * 5 + t;
        float z = 0.f;
        if (j < 32) {
#pragma unroll
            for (int u = 0; u < 48; u++) z += a[u] * sW0[u * 32 + j];
        } else {
            int g = j - 32, v = g / 3, i3 = g - v * 3;
            const float* a1 = a + 48;
#pragma unroll
            for (int u = 0; u < 48; u++) z += a1[u * 3 + i3] * sW1[u * 16 + v];
        }
        outr[j] += z;
    }
}

// ---------------------------------------------------------------------------
extern "C" void kernel_launch(void* const* d_in, const int* in_sizes, int n_in,
                              void* d_out, int out_size) {
    const float* node_input   = (const float*)d_in[0];
    const float* node_attr    = (const float*)d_in[1];
    const float* edge_attr    = (const float*)d_in[2];
    const float* edge_scalars = (const float*)d_in[3];
    const float* Wsc0 = (const float*)d_in[4];
    const float* Wsc1 = (const float*)d_in[5];
    const float* Wl10 = (const float*)d_in[6];
    const float* Wl11 = (const float*)d_in[7];
    const float* Wfc0 = (const float*)d_in[8];
    const float* Wfc1 = (const float*)d_in[9];
    const float* Wl20 = (const float*)d_in[10];
    const float* Wl21 = (const float*)d_in[11];
    const int*   edge_index = (const int*)d_in[12];
    float* out = (float*)d_out;

    zero_agg_kernel<<<(N_NODES * 192 / 4 + 255) / 256, 256>>>();
    node_kernel<<<(N_NODES + 15) / 16, 256>>>(node_input, node_attr,
                                              Wsc0, Wsc1, Wl10, Wl11, out);
    mlp_kernel<<<N_EDGES / MTILE, 256>>>(edge_scalars, Wfc0, Wfc1);
    msg_kernel<<<N_EDGES / ETILE, 512>>>(edge_attr, edge_index);
    final_kernel<<<(N_NODES + 15) / 16, 256>>>(Wl20, Wl21, out);
}

// round 4
// speedup vs baseline: 1.8057x; 1.2626x over previous
#include <cuda_runtime.h>
#include <math.h>

#define N_NODES 20000
#define N_EDGES 640000

// Scratch (allocation-free rule: __device__ globals)
__device__ float g_y[N_NODES * 80];       // 6.4 MB  l1-transformed node features
__device__ float g_agg[N_NODES * 192];    // 15.36 MB segment-sum accumulator (L2-resident)
__device__ float g_w[N_EDGES * 96];       // 245.8 MB per-edge MLP outputs (pre-scaled)

// ---------------------------------------------------------------------------
// f32x2 packed helpers (sm_100+): FFMA2 doubles fp32 FMA throughput.
// ---------------------------------------------------------------------------
__device__ __forceinline__ unsigned long long pack2(float x) {
    unsigned long long r;
    asm("mov.b64 %0, {%1, %1};" : "=l"(r) : "f"(x));
    return r;
}
__device__ __forceinline__ void ffma2(unsigned long long& d,
                                      unsigned long long a,
                                      unsigned long long b) {
    asm("fma.rn.f32x2 %0, %1, %2, %0;" : "+l"(d) : "l"(a), "l"(b));
}

__device__ __forceinline__ void red4(float* p, float a, float b, float c, float d) {
    asm volatile("red.global.add.v4.f32 [%0], {%1,%2,%3,%4};"
                 :: "l"(p), "f"(a), "f"(b), "f"(c), "f"(d) : "memory");
}

// ---------------------------------------------------------------------------
// Node transform: out = c_s * s, g_y = y.  16 nodes per 256-thread block;
// node rows staged through smem (coalesced float4).
// ---------------------------------------------------------------------------
__global__ void __launch_bounds__(256) node_kernel(
        const float* __restrict__ node_input,
        const float* __restrict__ node_attr,
        const float* __restrict__ Wsc0, const float* __restrict__ Wsc1,
        const float* __restrict__ Wl10, const float* __restrict__ Wl11,
        float* __restrict__ out) {
    __shared__ float s0[32 * 32], l0[32 * 32], s1[16 * 16], l1[16 * 16];
    __shared__ float sx[16 * 80];
    __shared__ float sa[16];
    for (int i = threadIdx.x; i < 1024; i += 256) { s0[i] = Wsc0[i]; l0[i] = Wl10[i]; }
    for (int i = threadIdx.x; i < 256;  i += 256) { s1[i] = Wsc1[i]; l1[i] = Wl11[i]; }

    int n0 = blockIdx.x * 16;
    int nodes = N_NODES - n0; if (nodes > 16) nodes = 16;
    for (int i = threadIdx.x; i < nodes * 20; i += 256)
        ((float4*)sx)[i] = ((const float4*)(node_input + (long long)n0 * 80))[i];
    if (threadIdx.x < nodes) sa[threadIdx.x] = node_attr[n0 + threadIdx.x];
    __syncthreads();

    int ln = threadIdx.x >> 4;      // local node 0..15
    int q  = threadIdx.x & 15;      // 5 outputs each
    if (ln >= nodes) return;
    const float* x = sx + ln * 80;
    float a = sa[ln];
    const float c_s = 0.3826834323650898f;   // sin(pi/8)
    float* outr = out + (long long)(n0 + ln) * 80;
    float* yr   = g_y + (long long)(n0 + ln) * 80;

#pragma unroll
    for (int t = 0; t < 5; t++) {
        int j = q * 5 + t;
        float acc_s = 0.f, acc_l = 0.f;
        if (j < 32) {
#pragma unroll
            for (int u = 0; u < 32; u++) {
                float xv = x[u];
                acc_s += xv * s0[u * 32 + j];
                acc_l += xv * l0[u * 32 + j];
            }
            const float inv = 0.17677669529663687f;  // 1/sqrt(32)
            outr[j] = c_s * acc_s * inv * a;
            yr[j]   = acc_l * inv * a;
        } else {
            int g = j - 32, v = g / 3, i3 = g - v * 3;
#pragma unroll
            for (int u = 0; u < 16; u++) {
                float xv = x[32 + u * 3 + i3];
                acc_s += xv * s1[u * 16 + v];
                acc_l += xv * l1[u * 16 + v];
            }
            outr[j] = c_s * acc_s * 0.25f * a;       // 1/sqrt(16)
            yr[j]   = acc_l * 0.25f * a;
        }
    }
}

// ---------------------------------------------------------------------------
// Edge MLP: 128 edges/CTA, 256 threads. Layer2 with packed f32x2 FMAs.
// Writes pre-scaled w (incl. 1/sqrt(64), 1/sqrt(32), 1/sqrt(3) on w_d cols).
// ---------------------------------------------------------------------------
#define MTILE 128
__global__ void __launch_bounds__(256) mlp_kernel(
        const float* __restrict__ edge_scalars,
        const float* __restrict__ Wfc0,
        const float* __restrict__ Wfc1) {
    __shared__ float sW0[10 * 64];
    __shared__ float sW1[64 * 96];
    __shared__ float sES[MTILE * 10];
    __shared__ float sHT[64 * 132];     // transposed h, padded for LDS.128 alignment

    const int tid = threadIdx.x;
    const int e0 = blockIdx.x * MTILE;

    const float invs10 = 0.31622776601683794f;        // 1/sqrt(10)
    for (int i = tid; i < 640; i += 256) sW0[i] = Wfc0[i] * invs10;
    const float w1scale = 0.02209708691207961f;       // 1/(8*sqrt(32))
    const float invs3   = 0.5773502691896258f;        // 1/sqrt(3)
    for (int i = tid; i < 6144; i += 256) {
        int col = i % 96;
        sW1[i] = Wfc1[i] * (col >= 80 ? w1scale * invs3 : w1scale);
    }
    for (int i = tid; i < MTILE * 10; i += 256) sES[i] = edge_scalars[e0 * 10 + i];
    __syncthreads();

    // ---- layer 1: 2 threads per edge, 32 h-cols each ----
    {
        int e  = tid >> 1;
        int c0 = (tid & 1) * 32;
        float es[10];
#pragma unroll
        for (int k = 0; k < 10; k++) es[k] = sES[e * 10 + k];
        float acc[32];
#pragma unroll
        for (int j = 0; j < 32; j++) acc[j] = 0.f;
#pragma unroll
        for (int k = 0; k < 10; k++) {
            float x = es[k];
#pragma unroll
            for (int j = 0; j < 32; j++) acc[j] += x * sW0[k * 64 + c0 + j];
        }
#pragma unroll
        for (int j = 0; j < 32; j++) {
            float aa = acc[j];
            sHT[(c0 + j) * 132 + e] = aa / (1.0f + __expf(-aa));
        }
    }
    __syncthreads();

    // ---- layer 2: thread = 4 edges x 12 cols (6 f32x2 col-pairs) ----
    {
        int eb = (tid >> 3) * 4;     // edge base (0..124)
        int c0 = (tid & 7) * 12;     // col base  (0..84)
        unsigned long long acc[4][6];
#pragma unroll
        for (int e = 0; e < 4; e++)
#pragma unroll
            for (int p = 0; p < 6; p++) acc[e][p] = 0ull;

#pragma unroll 4
        for (int k = 0; k < 64; k++) {
            float4 h4 = *(const float4*)&sHT[k * 132 + eb];
            unsigned long long hp0 = pack2(h4.x);
            unsigned long long hp1 = pack2(h4.y);
            unsigned long long hp2 = pack2(h4.z);
            unsigned long long hp3 = pack2(h4.w);
            const float* wr = &sW1[k * 96 + c0];
#pragma unroll
            for (int p = 0; p < 6; p++) {
                unsigned long long wp = *(const unsigned long long*)&wr[2 * p];
                ffma2(acc[0][p], hp0, wp);
                ffma2(acc[1][p], hp1, wp);
                ffma2(acc[2][p], hp2, wp);
                ffma2(acc[3][p], hp3, wp);
            }
        }
#pragma unroll
        for (int e = 0; e < 4; e++) {
            float* dst = g_w + (long long)(e0 + eb + e) * 96 + c0;
#pragma unroll
            for (int pp = 0; pp < 3; pp++) {
                ulonglong2 v;
                v.x = acc[e][2 * pp];
                v.y = acc[e][2 * pp + 1];
                *(ulonglong2*)(dst + 4 * pp) = v;
            }
        }
    }
}

// ---------------------------------------------------------------------------
// Message + scatter: one warp per edge, lanes cover contiguous fields.
// iter A: 32 lanes x float4 -> fields 0..127   (4 x 128B wavefronts)
// iter B: 16 lanes x float4 -> fields 128..191 (2 x 128B wavefronts)
// Field regions (all float4-pure): [0,32) m_a, [32,48) m_d, [48,144) m_b,
// [144,192) m_c.  No shared memory; everything via LDG (L1/L2 cached).
// ---------------------------------------------------------------------------
__device__ __forceinline__ float4 msg_val4(int f0,
        const float* __restrict__ we, const float* __restrict__ ye,
        float ea0, float e1x, float e1y, float e1z) {
    float4 r;
    if (f0 < 32) {                       // m_a: w_a[f]*y0[f]*e0
        float4 w4 = __ldg((const float4*)(we + f0));
        float4 y4 = __ldg((const float4*)(ye + f0));
        r.x = w4.x * y4.x * ea0; r.y = w4.y * y4.y * ea0;
        r.z = w4.z * y4.z * ea0; r.w = w4.w * y4.w * ea0;
    } else if (f0 < 48) {                // m_d: w_d[u]*dot(y1[u],e1)  (1/sqrt3 in w)
        int u0 = f0 - 32;
        float4 w4 = __ldg((const float4*)(we + 80 + u0));
        float4 ya = __ldg((const float4*)(ye + 32 + 3 * u0));
        float4 yb = __ldg((const float4*)(ye + 36 + 3 * u0));
        float4 yc = __ldg((const float4*)(ye + 40 + 3 * u0));
        float t[12] = {ya.x, ya.y, ya.z, ya.w, yb.x, yb.y, yb.z, yb.w,
                       yc.x, yc.y, yc.z, yc.w};
        r.x = w4.x * (t[0] * e1x + t[1]  * e1y + t[2]  * e1z);
        r.y = w4.y * (t[3] * e1x + t[4]  * e1y + t[5]  * e1z);
        r.z = w4.z * (t[6] * e1x + t[7]  * e1y + t[8]  * e1z);
        r.w = w4.w * (t[9] * e1x + t[10] * e1y + t[11] * e1z);
    } else if (f0 < 144) {               // m_b: w_b[c]*y0[c]*e1[i], g=f-48, c=g/3
        float v[4];
#pragma unroll
        for (int q = 0; q < 4; q++) {
            int g = f0 - 48 + q;
            int c = g / 3, i = g - 3 * c;
            float e1v = (i == 0) ? e1x : ((i == 1) ? e1y : e1z);
            v[q] = __ldg(we + 32 + c) * __ldg(ye + c) * e1v;
        }
        r.x = v[0]; r.y = v[1]; r.z = v[2]; r.w = v[3];
    } else {                             // m_c: w_c[u]*y1[u][i]*e0 = w_c[g/3]*ye[32+g]*e0
        int g0 = f0 - 144;
        float4 y4 = __ldg((const float4*)(ye + 32 + g0));
        float v[4];
        float yy[4] = {y4.x, y4.y, y4.z, y4.w};
#pragma unroll
        for (int q = 0; q < 4; q++) {
            int g = g0 + q;
            v[q] = __ldg(we + 64 + g / 3) * yy[q] * ea0;
        }
        r.x = v[0]; r.y = v[1]; r.z = v[2]; r.w = v[3];
    }
    return r;
}

__global__ void __launch_bounds__(256) msg_kernel(
        const float* __restrict__ edge_attr,
        const int* __restrict__ edge_index) {
    int warp = (blockIdx.x * 256 + threadIdx.x) >> 5;
    int lane = threadIdx.x & 31;
    if (warp >= N_EDGES) return;
    const int e = warp;

    int src = __ldg(edge_index + e);
    int dst = __ldg(edge_index + N_EDGES + e);
    const float* we = g_w + (long long)e * 96;
    const float* ye = g_y + (long long)src * 80;
    float4 ea = __ldg((const float4*)(edge_attr + e * 4));
    float ea0 = ea.x, e1x = ea.y, e1y = ea.z, e1z = ea.w;
    float* aggr = g_agg + (long long)dst * 192;

    // iter A: fields 0..127
    {
        int f0 = lane * 4;
        float4 v = msg_val4(f0, we, ye, ea0, e1x, e1y, e1z);
        red4(aggr + f0, v.x, v.y, v.z, v.w);
    }
    // iter B: fields 128..191
    if (lane < 16) {
        int f0 = 128 + lane * 4;
        float4 v = msg_val4(f0, we, ye, ea0, e1x, e1y, e1z);
        red4(aggr + f0, v.x, v.y, v.z, v.w);
    }
}

// ---------------------------------------------------------------------------
// Final: out += c_x * (agg @ W_l2) / sqrt(48).  16 nodes per 256-thread block.
// ---------------------------------------------------------------------------
__global__ void __launch_bounds__(256) final_kernel(
        const float* __restrict__ Wl20,
        const float* __restrict__ Wl21,
        float* __restrict__ out) {
    __shared__ float sW0[48 * 32];
    __shared__ float sW1[48 * 16];
    __shared__ float sa[16 * 192];
    const float sc = 0.9238795325112867f * 0.14433756729740643f;  // cos(pi/8)/sqrt(48)
    for (int i = threadIdx.x; i < 48 * 32; i += 256) sW0[i] = Wl20[i] * sc;
    for (int i = threadIdx.x; i < 48 * 16; i += 256) sW1[i] = Wl21[i] * sc;

    int n0 = blockIdx.x * 16;
    int nodes = N_NODES - n0; if (nodes > 16) nodes = 16;
    for (int i = threadIdx.x; i < nodes * 48; i += 256)
        ((float4*)sa)[i] = ((const float4*)(g_agg + (long long)n0 * 192))[i];
    __syncthreads();

    int ln = threadIdx.x >> 4;
    int q  = threadIdx.x & 15;
    if (ln >= nodes) return;
    const float* a = sa + ln * 192;
    float* outr = out + (long long)(n0 + ln) * 80;

#pragma unroll
    for (int t = 0; t < 5; t++) {
        int j = q * 5 + t;
        float z = 0.f;
        if (j < 32) {
#pragma unroll
            for (int u = 0; u < 48; u++) z += a[u] * sW0[u * 32 + j];
        } else {
            int g = j - 32, v = g / 3, i3 = g - v * 3;
            const float* a1 = a + 48;
#pragma unroll
            for (int u = 0; u < 48; u++) z += a1[u * 3 + i3] * sW1[u * 16 + v];
        }
        outr[j] += z;
    }
}

// ---------------------------------------------------------------------------
extern "C" void kernel_launch(void* const* d_in, const int* in_sizes, int n_in,
                              void* d_out, int out_size) {
    const float* node_input   = (const float*)d_in[0];
    const float* node_attr    = (const float*)d_in[1];
    const float* edge_attr    = (const float*)d_in[2];
    const float* edge_scalars = (const float*)d_in[3];
    const float* Wsc0 = (const float*)d_in[4];
    const float* Wsc1 = (const float*)d_in[5];
    const float* Wl10 = (const float*)d_in[6];
    const float* Wl11 = (const float*)d_in[7];
    const float* Wfc0 = (const float*)d_in[8];
    const float* Wfc1 = (const float*)d_in[9];
    const float* Wl20 = (const float*)d_in[10];
    const float* Wl21 = (const float*)d_in[11];
    const int*   edge_index = (const int*)d_in[12];
    float* out = (float*)d_out;

    void* agg_ptr = nullptr;
    cudaGetSymbolAddress(&agg_ptr, g_agg);
    cudaMemsetAsync(agg_ptr, 0, (size_t)N_NODES * 192 * sizeof(float));

    node_kernel<<<(N_NODES + 15) / 16, 256>>>(node_input, node_attr,
                                              Wsc0, Wsc1, Wl10, Wl11, out);
    mlp_kernel<<<N_EDGES / MTILE, 256>>>(edge_scalars, Wfc0, Wfc1);
    msg_kernel<<<N_EDGES / 8, 256>>>(edge_attr, edge_index);
    final_kernel<<<(N_NODES + 15) / 16, 256>>>(Wl20, Wl21, out);
}

// round 13
// speedup vs baseline: 1.8986x; 1.0515x over previous
#include <cuda_runtime.h>
#include <math.h>

#define N_NODES 20000
#define N_EDGES 640000

// Scratch (allocation-free rule: __device__ globals)
__device__ float g_y[N_NODES * 80];       // 6.4 MB  l1-transformed node features
__device__ float g_agg[N_NODES * 192];    // 15.36 MB segment-sum accumulator (L2-resident)
__device__ float g_w[N_EDGES * 96];       // 245.8 MB per-edge MLP outputs (pre-scaled)

// ---------------------------------------------------------------------------
// f32x2 packed helpers (sm_100+): FFMA2 doubles fp32 FMA throughput.
// ---------------------------------------------------------------------------
__device__ __forceinline__ unsigned long long pack2(float x) {
    unsigned long long r;
    asm("mov.b64 %0, {%1, %1};" : "=l"(r) : "f"(x));
    return r;
}
__device__ __forceinline__ void ffma2(unsigned long long& d,
                                      unsigned long long a,
                                      unsigned long long b) {
    asm("fma.rn.f32x2 %0, %1, %2, %0;" : "+l"(d) : "l"(a), "l"(b));
}
__device__ __forceinline__ void red4(float* p, float a, float b, float c, float d) {
    asm volatile("red.global.add.v4.f32 [%0], {%1,%2,%3,%4};"
                 :: "l"(p), "f"(a), "f"(b), "f"(c), "f"(d) : "memory");
}

// ---------------------------------------------------------------------------
// Node transform: out = c_s * s, g_y = y.  16 nodes per 256-thread block;
// outputs strided (j = q + 16t) for uniform branches + high ILP.
// ---------------------------------------------------------------------------
__global__ void __launch_bounds__(256) node_kernel(
        const float* __restrict__ node_input,
        const float* __restrict__ node_attr,
        const float* __restrict__ Wsc0, const float* __restrict__ Wsc1,
        const float* __restrict__ Wl10, const float* __restrict__ Wl11,
        float* __restrict__ out) {
    __shared__ float s0[32 * 32], l0[32 * 32], s1[16 * 16], l1[16 * 16];
    __shared__ float sx[16 * 80];
    __shared__ float sa[16];
    for (int i = threadIdx.x; i < 1024; i += 256) { s0[i] = Wsc0[i]; l0[i] = Wl10[i]; }
    for (int i = threadIdx.x; i < 256;  i += 256) { s1[i] = Wsc1[i]; l1[i] = Wl11[i]; }

    int n0 = blockIdx.x * 16;
    int nodes = N_NODES - n0; if (nodes > 16) nodes = 16;
    for (int i = threadIdx.x; i < nodes * 20; i += 256)
        ((float4*)sx)[i] = ((const float4*)(node_input + (long long)n0 * 80))[i];
    if (threadIdx.x < nodes) sa[threadIdx.x] = node_attr[n0 + threadIdx.x];
    __syncthreads();

    int ln = threadIdx.x >> 4;      // local node 0..15
    int q  = threadIdx.x & 15;      // outputs j = q + 16t, t=0..4
    if (ln >= nodes) return;
    const float* x = sx + ln * 80;
    float a = sa[ln];
    const float c_s = 0.3826834323650898f;   // sin(pi/8)
    float* outr = out + (long long)(n0 + ln) * 80;
    float* yr   = g_y + (long long)(n0 + ln) * 80;

    // scalar outputs j = q, q+16  (both < 32)
    {
        float as0 = 0.f, al0 = 0.f, as1 = 0.f, al1 = 0.f;
#pragma unroll
        for (int u = 0; u < 32; u++) {
            float xv = x[u];
            as0 += xv * s0[u * 32 + q];
            al0 += xv * l0[u * 32 + q];
            as1 += xv * s0[u * 32 + q + 16];
            al1 += xv * l0[u * 32 + q + 16];
        }
        const float inv = 0.17677669529663687f;  // 1/sqrt(32)
        outr[q]      = c_s * as0 * inv * a;
        yr[q]        = al0 * inv * a;
        outr[q + 16] = c_s * as1 * inv * a;
        yr[q + 16]   = al1 * inv * a;
    }
    // vector outputs j = q+32, q+48, q+64  (all >= 32)
    {
        float zs[3] = {0.f, 0.f, 0.f}, zl[3] = {0.f, 0.f, 0.f};
        int v[3], i3[3];
#pragma unroll
        for (int t = 0; t < 3; t++) {
            int g = q + 16 * t;       // 0..47
            v[t] = g / 3; i3[t] = g - 3 * v[t];
        }
#pragma unroll
        for (int u = 0; u < 16; u++) {
#pragma unroll
            for (int t = 0; t < 3; t++) {
                float xv = x[32 + u * 3 + i3[t]];
                zs[t] += xv * s1[u * 16 + v[t]];
                zl[t] += xv * l1[u * 16 + v[t]];
            }
        }
#pragma unroll
        for (int t = 0; t < 3; t++) {
            int j = q + 32 + 16 * t;
            outr[j] = c_s * zs[t] * 0.25f * a;   // 1/sqrt(16)
            yr[j]   = zl[t] * 0.25f * a;
        }
    }
}

// ---------------------------------------------------------------------------
// Edge MLP (R4-proven): 128 edges/CTA, 256 threads. Layer2 with packed f32x2
// FMAs. Writes pre-scaled w (incl. 1/sqrt(64), 1/sqrt(32), 1/sqrt(3) on w_d).
// ---------------------------------------------------------------------------
#define MTILE 128
__global__ void __launch_bounds__(256) mlp_kernel(
        const float* __restrict__ edge_scalars,
        const float* __restrict__ Wfc0,
        const float* __restrict__ Wfc1) {
    __shared__ float sW0[10 * 64];
    __shared__ float sW1[64 * 96];
    __shared__ float sES[MTILE * 10];
    __shared__ float sHT[64 * 132];     // transposed h, padded for LDS.128 alignment

    const int tid = threadIdx.x;
    const int e0 = blockIdx.x * MTILE;

    const float invs10 = 0.31622776601683794f;        // 1/sqrt(10)
    for (int i = tid; i < 640; i += 256) sW0[i] = Wfc0[i] * invs10;
    const float w1scale = 0.02209708691207961f;       // 1/(8*sqrt(32))
    const float invs3   = 0.5773502691896258f;        // 1/sqrt(3)
    for (int i = tid; i < 6144; i += 256) {
        int col = i % 96;
        sW1[i] = Wfc1[i] * (col >= 80 ? w1scale * invs3 : w1scale);
    }
    for (int i = tid; i < MTILE * 10; i += 256) sES[i] = edge_scalars[e0 * 10 + i];
    __syncthreads();

    // ---- layer 1: 2 threads per edge, 32 h-cols each ----
    {
        int e  = tid >> 1;
        int c0 = (tid & 1) * 32;
        float es[10];
#pragma unroll
        for (int k = 0; k < 10; k++) es[k] = sES[e * 10 + k];
        float acc[32];
#pragma unroll
        for (int j = 0; j < 32; j++) acc[j] = 0.f;
#pragma unroll
        for (int k = 0; k < 10; k++) {
            float x = es[k];
#pragma unroll
            for (int j = 0; j < 32; j++) acc[j] += x * sW0[k * 64 + c0 + j];
        }
#pragma unroll
        for (int j = 0; j < 32; j++) {
            float aa = acc[j];
            sHT[(c0 + j) * 132 + e] = aa / (1.0f + __expf(-aa));
        }
    }
    __syncthreads();

    // ---- layer 2: thread = 4 edges x 12 cols (6 f32x2 col-pairs) ----
    {
        int eb = (tid >> 3) * 4;     // edge base (0..124)
        int c0 = (tid & 7) * 12;     // col base  (0..84)
        unsigned long long acc[4][6];
#pragma unroll
        for (int e = 0; e < 4; e++)
#pragma unroll
            for (int p = 0; p < 6; p++) acc[e][p] = 0ull;

#pragma unroll 4
        for (int k = 0; k < 64; k++) {
            float4 h4 = *(const float4*)&sHT[k * 132 + eb];
            unsigned long long hp0 = pack2(h4.x);
            unsigned long long hp1 = pack2(h4.y);
            unsigned long long hp2 = pack2(h4.z);
            unsigned long long hp3 = pack2(h4.w);
            const float* wr = &sW1[k * 96 + c0];
#pragma unroll
            for (int p = 0; p < 6; p++) {
                unsigned long long wp = *(const unsigned long long*)&wr[2 * p];
                ffma2(acc[0][p], hp0, wp);
                ffma2(acc[1][p], hp1, wp);
                ffma2(acc[2][p], hp2, wp);
                ffma2(acc[3][p], hp3, wp);
            }
        }
#pragma unroll
        for (int e = 0; e < 4; e++) {
            float* dst = g_w + (long long)(e0 + eb + e) * 96 + c0;
#pragma unroll
            for (int pp = 0; pp < 3; pp++) {
                ulonglong2 v;
                v.x = acc[e][2 * pp];
                v.y = acc[e][2 * pp + 1];
                *(ulonglong2*)(dst + 4 * pp) = v;
            }
        }
    }
}

// ---------------------------------------------------------------------------
// Message + scatter (R4-proven): one warp per edge, contiguous fields.
// iter A: 32 lanes x float4 -> fields 0..127; iter B: 16 lanes -> 128..191.
// ---------------------------------------------------------------------------
__device__ __forceinline__ float4 msg_val4(int f0,
        const float* __restrict__ we, const float* __restrict__ ye,
        float ea0, float e1x, float e1y, float e1z) {
    float4 r;
    if (f0 < 32) {                       // m_a
        float4 w4 = __ldg((const float4*)(we + f0));
        float4 y4 = __ldg((const float4*)(ye + f0));
        r.x = w4.x * y4.x * ea0; r.y = w4.y * y4.y * ea0;
        r.z = w4.z * y4.z * ea0; r.w = w4.w * y4.w * ea0;
    } else if (f0 < 48) {                // m_d (1/sqrt3 folded into w)
        int u0 = f0 - 32;
        float4 w4 = __ldg((const float4*)(we + 80 + u0));
        float4 ya = __ldg((const float4*)(ye + 32 + 3 * u0));
        float4 yb = __ldg((const float4*)(ye + 36 + 3 * u0));
        float4 yc = __ldg((const float4*)(ye + 40 + 3 * u0));
        float t[12] = {ya.x, ya.y, ya.z, ya.w, yb.x, yb.y, yb.z, yb.w,
                       yc.x, yc.y, yc.z, yc.w};
        r.x = w4.x * (t[0] * e1x + t[1]  * e1y + t[2]  * e1z);
        r.y = w4.y * (t[3] * e1x + t[4]  * e1y + t[5]  * e1z);
        r.z = w4.z * (t[6] * e1x + t[7]  * e1y + t[8]  * e1z);
        r.w = w4.w * (t[9] * e1x + t[10] * e1y + t[11] * e1z);
    } else if (f0 < 144) {               // m_b
        float v[4];
#pragma unroll
        for (int q = 0; q < 4; q++) {
            int g = f0 - 48 + q;
            int c = g / 3, i = g - 3 * c;
            float e1v = (i == 0) ? e1x : ((i == 1) ? e1y : e1z);
            v[q] = __ldg(we + 32 + c) * __ldg(ye + c) * e1v;
        }
        r.x = v[0]; r.y = v[1]; r.z = v[2]; r.w = v[3];
    } else {                             // m_c
        int g0 = f0 - 144;
        float4 y4 = __ldg((const float4*)(ye + 32 + g0));
        float yy[4] = {y4.x, y4.y, y4.z, y4.w};
        float v[4];
#pragma unroll
        for (int q = 0; q < 4; q++) v[q] = __ldg(we + 64 + (g0 + q) / 3) * yy[q] * ea0;
        r.x = v[0]; r.y = v[1]; r.z = v[2]; r.w = v[3];
    }
    return r;
}

__global__ void __launch_bounds__(256) msg_kernel(
        const float* __restrict__ edge_attr,
        const int* __restrict__ edge_index) {
    int warp = (blockIdx.x * 256 + threadIdx.x) >> 5;
    int lane = threadIdx.x & 31;
    if (warp >= N_EDGES) return;
    const int e = warp;

    int src = __ldg(edge_index + e);
    int dst = __ldg(edge_index + N_EDGES + e);
    const float* we = g_w + (long long)e * 96;
    const float* ye = g_y + (long long)src * 80;
    float4 ea = __ldg((const float4*)(edge_attr + e * 4));
    float* aggr = g_agg + (long long)dst * 192;

    {
        int f0 = lane * 4;
        float4 v = msg_val4(f0, we, ye, ea.x, ea.y, ea.z, ea.w);
        red4(aggr + f0, v.x, v.y, v.z, v.w);
    }
    if (lane < 16) {
        int f0 = 128 + lane * 4;
        float4 v = msg_val4(f0, we, ye, ea.x, ea.y, ea.z, ea.w);
        red4(aggr + f0, v.x, v.y, v.z, v.w);
    }
}

// ---------------------------------------------------------------------------
// Final: out += c_x * (agg @ W_l2) / sqrt(48).  Strided outputs (j = q+16t),
// 5 independent accumulators, FULL 48-term reduction for every output.
// ---------------------------------------------------------------------------
__global__ void __launch_bounds__(256) final_kernel(
        const float* __restrict__ Wl20,
        const float* __restrict__ Wl21,
        float* __restrict__ out) {
    __shared__ float sW0[48 * 32];
    __shared__ float sW1[48 * 16];
    __shared__ float sa[16 * 192];
    const float sc = 0.9238795325112867f * 0.14433756729740643f;  // cos(pi/8)/sqrt(48)
    for (int i = threadIdx.x; i < 48 * 32; i += 256) sW0[i] = Wl20[i] * sc;
    for (int i = threadIdx.x; i < 48 * 16; i += 256) sW1[i] = Wl21[i] * sc;

    int n0 = blockIdx.x * 16;
    int nodes = N_NODES - n0; if (nodes > 16) nodes = 16;
    for (int i = threadIdx.x; i < nodes * 48; i += 256)
        ((float4*)sa)[i] = ((const float4*)(g_agg + (long long)n0 * 192))[i];
    __syncthreads();

    int ln = threadIdx.x >> 4;
    int q  = threadIdx.x & 15;
    if (ln >= nodes) return;
    const float* a  = sa + ln * 192;
    const float* a1 = a + 48;
    float* outr = out + (long long)(n0 + ln) * 80;

    float z0 = 0.f, z1 = 0.f, z2 = 0.f, z3 = 0.f, z4 = 0.f;
    int v2, i2, v3, i3, v4, i4;
    { int g = q;      v2 = g / 3; i2 = g - 3 * v2; }
    { int g = q + 16; v3 = g / 3; i3 = g - 3 * v3; }
    { int g = q + 32; v4 = g / 3; i4 = g - 3 * v4; }
#pragma unroll
    for (int u = 0; u < 48; u++) {
        float au = a[u];
        z0 += au * sW0[u * 32 + q];
        z1 += au * sW0[u * 32 + q + 16];
        z2 += a1[u * 3 + i2] * sW1[u * 16 + v2];
        z3 += a1[u * 3 + i3] * sW1[u * 16 + v3];
        z4 += a1[u * 3 + i4] * sW1[u * 16 + v4];
    }
    outr[q]      += z0;
    outr[q + 16] += z1;
    outr[q + 32] += z2;
    outr[q + 48] += z3;
    outr[q + 64] += z4;
}

// ---------------------------------------------------------------------------
extern "C" void kernel_launch(void* const* d_in, const int* in_sizes, int n_in,
                              void* d_out, int out_size) {
    const float* node_input   = (const float*)d_in[0];
    const float* node_attr    = (const float*)d_in[1];
    const float* edge_attr    = (const float*)d_in[2];
    const float* edge_scalars = (const float*)d_in[3];
    const float* Wsc0 = (const float*)d_in[4];
    const float* Wsc1 = (const float*)d_in[5];
    const float* Wl10 = (const float*)d_in[6];
    const float* Wl11 = (const float*)d_in[7];
    const float* Wfc0 = (const float*)d_in[8];
    const float* Wfc1 = (const float*)d_in[9];
    const float* Wl20 = (const float*)d_in[10];
    const float* Wl21 = (const float*)d_in[11];
    const int*   edge_index = (const int*)d_in[12];
    float* out = (float*)d_out;

    void* agg_ptr = nullptr;
    cudaGetSymbolAddress(&agg_ptr, g_agg);
    cudaMemsetAsync(agg_ptr, 0, (size_t)N_NODES * 192 * sizeof(float));

    node_kernel<<<(N_NODES + 15) / 16, 256>>>(node_input, node_attr,
                                              Wsc0, Wsc1, Wl10, Wl11, out);
    mlp_kernel<<<N_EDGES / MTILE, 256>>>(edge_scalars, Wfc0, Wfc1);
    msg_kernel<<<N_EDGES / 8, 256>>>(edge_attr, edge_index);
    final_kernel<<<(N_NODES + 15) / 16, 256>>>(Wl20, Wl21, out);
}

// round 15
// speedup vs baseline: 2.2442x; 1.1820x over previous
#include <cuda_runtime.h>
#include <math.h>

#define N_NODES 20000
#define N_EDGES 640000
#define MTILE 128

// Scratch (allocation-free rule: __device__ globals)
__device__ float g_y[N_NODES * 80];       // 6.4 MB  l1-transformed node features
__device__ float g_agg[N_NODES * 192];    // 15.36 MB segment-sum accumulator (L2-resident)

// ---------------------------------------------------------------------------
// f32x2 packed helpers (sm_100+): FFMA2 doubles fp32 FMA throughput.
// ---------------------------------------------------------------------------
__device__ __forceinline__ unsigned long long pack2(float x) {
    unsigned long long r;
    asm("mov.b64 %0, {%1, %1};" : "=l"(r) : "f"(x));
    return r;
}
__device__ __forceinline__ void ffma2(unsigned long long& d,
                                      unsigned long long a,
                                      unsigned long long b) {
    asm("fma.rn.f32x2 %0, %1, %2, %0;" : "+l"(d) : "l"(a), "l"(b));
}
__device__ __forceinline__ void red4(float* p, float a, float b, float c, float d) {
    asm volatile("red.global.add.v4.f32 [%0], {%1,%2,%3,%4};"
                 :: "l"(p), "f"(a), "f"(b), "f"(c), "f"(d) : "memory");
}

// ---------------------------------------------------------------------------
// Node transform: out = c_s * s, g_y = y.  16 nodes per 256-thread block;
// outputs strided (j = q + 16t) for uniform branches + high ILP.
// ---------------------------------------------------------------------------
__global__ void __launch_bounds__(256) node_kernel(
        const float* __restrict__ node_input,
        const float* __restrict__ node_attr,
        const float* __restrict__ Wsc0, const float* __restrict__ Wsc1,
        const float* __restrict__ Wl10, const float* __restrict__ Wl11,
        float* __restrict__ out) {
    __shared__ float s0[32 * 32], l0[32 * 32], s1[16 * 16], l1[16 * 16];
    __shared__ float sx[16 * 80];
    __shared__ float sa[16];
    for (int i = threadIdx.x; i < 1024; i += 256) { s0[i] = Wsc0[i]; l0[i] = Wl10[i]; }
    for (int i = threadIdx.x; i < 256;  i += 256) { s1[i] = Wsc1[i]; l1[i] = Wl11[i]; }

    int n0 = blockIdx.x * 16;
    int nodes = N_NODES - n0; if (nodes > 16) nodes = 16;
    for (int i = threadIdx.x; i < nodes * 20; i += 256)
        ((float4*)sx)[i] = ((const float4*)(node_input + (long long)n0 * 80))[i];
    if (threadIdx.x < nodes) sa[threadIdx.x] = node_attr[n0 + threadIdx.x];
    __syncthreads();

    int ln = threadIdx.x >> 4;      // local node 0..15
    int q  = threadIdx.x & 15;      // outputs j = q + 16t, t=0..4
    if (ln >= nodes) return;
    const float* x = sx + ln * 80;
    float a = sa[ln];
    const float c_s = 0.3826834323650898f;   // sin(pi/8)
    float* outr = out + (long long)(n0 + ln) * 80;
    float* yr   = g_y + (long long)(n0 + ln) * 80;

    // scalar outputs j = q, q+16  (both < 32)
    {
        float as0 = 0.f, al0 = 0.f, as1 = 0.f, al1 = 0.f;
#pragma unroll
        for (int u = 0; u < 32; u++) {
            float xv = x[u];
            as0 += xv * s0[u * 32 + q];
            al0 += xv * l0[u * 32 + q];
            as1 += xv * s0[u * 32 + q + 16];
            al1 += xv * l0[u * 32 + q + 16];
        }
        const float inv = 0.17677669529663687f;  // 1/sqrt(32)
        outr[q]      = c_s * as0 * inv * a;
        yr[q]        = al0 * inv * a;
        outr[q + 16] = c_s * as1 * inv * a;
        yr[q + 16]   = al1 * inv * a;
    }
    // vector outputs j = q+32, q+48, q+64  (all >= 32)
    {
        float zs[3] = {0.f, 0.f, 0.f}, zl[3] = {0.f, 0.f, 0.f};
        int v[3], i3[3];
#pragma unroll
        for (int t = 0; t < 3; t++) {
            int g = q + 16 * t;       // 0..47
            v[t] = g / 3; i3[t] = g - 3 * v[t];
        }
#pragma unroll
        for (int u = 0; u < 16; u++) {
#pragma unroll
            for (int t = 0; t < 3; t++) {
                float xv = x[32 + u * 3 + i3[t]];
                zs[t] += xv * s1[u * 16 + v[t]];
                zl[t] += xv * l1[u * 16 + v[t]];
            }
        }
#pragma unroll
        for (int t = 0; t < 3; t++) {
            int j = q + 32 + 16 * t;
            outr[j] = c_s * zs[t] * 0.25f * a;   // 1/sqrt(16)
            yr[j]   = zl[t] * 0.25f * a;
        }
    }
}

// ---------------------------------------------------------------------------
// Message value helper: 4 contiguous fields starting at f0 (f0 % 4 == 0).
// Regions (float4-pure): [0,32) m_a, [32,48) m_d, [48,144) m_b, [144,192) m_c.
// we points to smem, ye to global.
// ---------------------------------------------------------------------------
__device__ __forceinline__ float4 msg_val4(int f0,
        const float* we, const float* __restrict__ ye,
        float ea0, float e1x, float e1y, float e1z) {
    float4 r;
    if (f0 < 32) {                       // m_a: w_a[f]*y0[f]*e0
        float4 w4 = *(const float4*)(we + f0);
        float4 y4 = __ldg((const float4*)(ye + f0));
        r.x = w4.x * y4.x * ea0; r.y = w4.y * y4.y * ea0;
        r.z = w4.z * y4.z * ea0; r.w = w4.w * y4.w * ea0;
    } else if (f0 < 48) {                // m_d: w_d[u]*dot(y1[u],e1)  (1/sqrt3 in w)
        int u0 = f0 - 32;
        float4 w4 = *(const float4*)(we + 80 + u0);
        float4 ya = __ldg((const float4*)(ye + 32 + 3 * u0));
        float4 yb = __ldg((const float4*)(ye + 36 + 3 * u0));
        float4 yc = __ldg((const float4*)(ye + 40 + 3 * u0));
        float t[12] = {ya.x, ya.y, ya.z, ya.w, yb.x, yb.y, yb.z, yb.w,
                       yc.x, yc.y, yc.z, yc.w};
        r.x = w4.x * (t[0] * e1x + t[1]  * e1y + t[2]  * e1z);
        r.y = w4.y * (t[3] * e1x + t[4]  * e1y + t[5]  * e1z);
        r.z = w4.z * (t[6] * e1x + t[7]  * e1y + t[8]  * e1z);
        r.w = w4.w * (t[9] * e1x + t[10] * e1y + t[11] * e1z);
    } else if (f0 < 144) {               // m_b: w_b[c]*y0[c]*e1[i], g=f-48, c=g/3
        float v[4];
#pragma unroll
        for (int q = 0; q < 4; q++) {
            int g = f0 - 48 + q;
            int c = g / 3, i = g - 3 * c;
            float e1v = (i == 0) ? e1x : ((i == 1) ? e1y : e1z);
            v[q] = we[32 + c] * __ldg(ye + c) * e1v;
        }
        r.x = v[0]; r.y = v[1]; r.z = v[2]; r.w = v[3];
    } else {                             // m_c: w_c[g/3]*ye[32+g]*e0
        int g0 = f0 - 144;
        float4 y4 = __ldg((const float4*)(ye + 32 + g0));
        float yy[4] = {y4.x, y4.y, y4.z, y4.w};
        float v[4];
#pragma unroll
        for (int q = 0; q < 4; q++) v[q] = we[64 + (g0 + q) / 3] * yy[q] * ea0;
        r.x = v[0]; r.y = v[1]; r.z = v[2]; r.w = v[3];
    }
    return r;
}

// ---------------------------------------------------------------------------
// Fused edge kernel: MLP(10->64->96) -> smem -> message + atomic scatter.
// 128 edges/CTA, 256 threads, dynamic smem 76 KB (2 CTAs/SM).
// Union region U (12288 floats): phase 1-2 = sHT(8448) + sES(1280);
// phase 3 = sWo(12288).
// ---------------------------------------------------------------------------
__global__ void __launch_bounds__(256) edge_kernel(
        const float* __restrict__ edge_scalars,
        const float* __restrict__ edge_attr,
        const int* __restrict__ edge_index,
        const float* __restrict__ Wfc0,
        const float* __restrict__ Wfc1) {
    extern __shared__ float sm[];
    float* sW0 = sm;                 // 640
    float* sW1 = sm + 640;           // 6144
    float* U   = sm + 6784;          // 12288 union
    float* sHT = U;                  // 64 x 132 (phases 1-2)
    float* sES = U + 8448;           // 1280     (phase 1)
    float* sWo = U;                  // 128 x 96 (phase 3)

    const int tid = threadIdx.x;
    const int e0 = blockIdx.x * MTILE;

    const float invs10 = 0.31622776601683794f;        // 1/sqrt(10)
    for (int i = tid; i < 640; i += 256) sW0[i] = Wfc0[i] * invs10;
    const float w1scale = 0.02209708691207961f;       // 1/(8*sqrt(32)) = 1/sqrt(64*32)
    const float invs3   = 0.5773502691896258f;        // 1/sqrt(3)
    for (int i = tid; i < 6144; i += 256) {
        int col = i % 96;
        sW1[i] = Wfc1[i] * (col >= 80 ? w1scale * invs3 : w1scale);
    }
    for (int i = tid; i < MTILE * 10; i += 256) sES[i] = edge_scalars[e0 * 10 + i];
    __syncthreads();

    // ---- layer 1: 2 threads per edge, 32 h-cols each ----
    {
        int e  = tid >> 1;
        int c0 = (tid & 1) * 32;
        float es[10];
#pragma unroll
        for (int k = 0; k < 10; k++) es[k] = sES[e * 10 + k];
        float acc[32];
#pragma unroll
        for (int j = 0; j < 32; j++) acc[j] = 0.f;
#pragma unroll
        for (int k = 0; k < 10; k++) {
            float x = es[k];
#pragma unroll
            for (int j = 0; j < 32; j++) acc[j] += x * sW0[k * 64 + c0 + j];
        }
#pragma unroll
        for (int j = 0; j < 32; j++) {
            float aa = acc[j];
            sHT[(c0 + j) * 132 + e] = aa / (1.0f + __expf(-aa));
        }
    }
    __syncthreads();

    // ---- layer 2: thread = 4 edges x 12 cols (6 f32x2 col-pairs) ----
    unsigned long long acc[4][6];
    {
        int eb = (tid >> 3) * 4;     // edge base (0..124)
        int c0 = (tid & 7) * 12;     // col base  (0..84)
#pragma unroll
        for (int e = 0; e < 4; e++)
#pragma unroll
            for (int p = 0; p < 6; p++) acc[e][p] = 0ull;

#pragma unroll 4
        for (int k = 0; k < 64; k++) {
            float4 h4 = *(const float4*)&sHT[k * 132 + eb];
            unsigned long long hp0 = pack2(h4.x);
            unsigned long long hp1 = pack2(h4.y);
            unsigned long long hp2 = pack2(h4.z);
            unsigned long long hp3 = pack2(h4.w);
            const float* wr = &sW1[k * 96 + c0];
#pragma unroll
            for (int p = 0; p < 6; p++) {
                unsigned long long wp = *(const unsigned long long*)&wr[2 * p];
                ffma2(acc[0][p], hp0, wp);
                ffma2(acc[1][p], hp1, wp);
                ffma2(acc[2][p], hp2, wp);
                ffma2(acc[3][p], hp3, wp);
            }
        }
    }
    __syncthreads();   // done reading sHT; U becomes sWo

    {
        int eb = (tid >> 3) * 4;
        int c0 = (tid & 7) * 12;
#pragma unroll
        for (int e = 0; e < 4; e++) {
            float* dst = sWo + (eb + e) * 96 + c0;
#pragma unroll
            for (int pp = 0; pp < 3; pp++) {
                ulonglong2 v;
                v.x = acc[e][2 * pp];
                v.y = acc[e][2 * pp + 1];
                *(ulonglong2*)(dst + 4 * pp) = v;
            }
        }
    }
    __syncthreads();

    // ---- phase 3: message + scatter, warp-per-edge, 16 edges per warp ----
    const int warp = tid >> 5;
    const int lane = tid & 31;
    for (int t = warp; t < MTILE; t += 8) {
        const int e = e0 + t;
        int src = __ldg(edge_index + e);
        int dst = __ldg(edge_index + N_EDGES + e);
        const float* we = sWo + t * 96;
        const float* ye = g_y + (long long)src * 80;
        float4 ea = __ldg((const float4*)(edge_attr + e * 4));
        float* aggr = g_agg + (long long)dst * 192;

        {   // fields 0..127
            int f0 = lane * 4;
            float4 v = msg_val4(f0, we, ye, ea.x, ea.y, ea.z, ea.w);
            red4(aggr + f0, v.x, v.y, v.z, v.w);
        }
        if (lane < 16) {   // fields 128..191
            int f0 = 128 + lane * 4;
            float4 v = msg_val4(f0, we, ye, ea.x, ea.y, ea.z, ea.w);
            red4(aggr + f0, v.x, v.y, v.z, v.w);
        }
    }
}

// ---------------------------------------------------------------------------
// Final: out += c_x * (agg @ W_l2) / sqrt(48).  Strided outputs (j = q+16t),
// 5 independent accumulators, FULL 48-term reduction for every output.
// ---------------------------------------------------------------------------
__global__ void __launch_bounds__(256) final_kernel(
        const float* __restrict__ Wl20,
        const float* __restrict__ Wl21,
        float* __restrict__ out) {
    __shared__ float sW0[48 * 32];
    __shared__ float sW1[48 * 16];
    __shared__ float sa[16 * 192];
    const float sc = 0.9238795325112867f * 0.14433756729740643f;  // cos(pi/8)/sqrt(48)
    for (int i = threadIdx.x; i < 48 * 32; i += 256) sW0[i] = Wl20[i] * sc;
    for (int i = threadIdx.x; i < 48 * 16; i += 256) sW1[i] = Wl21[i] * sc;

    int n0 = blockIdx.x * 16;
    int nodes = N_NODES - n0; if (nodes > 16) nodes = 16;
    for (int i = threadIdx.x; i < nodes * 48; i += 256)
        ((float4*)sa)[i] = ((const float4*)(g_agg + (long long)n0 * 192))[i];
    __syncthreads();

    int ln = threadIdx.x >> 4;
    int q  = threadIdx.x & 15;
    if (ln >= nodes) return;
    const float* a  = sa + ln * 192;
    const float* a1 = a + 48;
    float* outr = out + (long long)(n0 + ln) * 80;

    float z0 = 0.f, z1 = 0.f, z2 = 0.f, z3 = 0.f, z4 = 0.f;
    int v2, i2, v3, i3, v4, i4;
    { int g = q;      v2 = g / 3; i2 = g - 3 * v2; }
    { int g = q + 16; v3 = g / 3; i3 = g - 3 * v3; }
    { int g = q + 32; v4 = g / 3; i4 = g - 3 * v4; }
#pragma unroll
    for (int u = 0; u < 48; u++) {
        float au = a[u];
        z0 += au * sW0[u * 32 + q];
        z1 += au * sW0[u * 32 + q + 16];
        z2 += a1[u * 3 + i2] * sW1[u * 16 + v2];
        z3 += a1[u * 3 + i3] * sW1[u * 16 + v3];
        z4 += a1[u * 3 + i4] * sW1[u * 16 + v4];
    }
    outr[q]      += z0;
    outr[q + 16] += z1;
    outr[q + 32] += z2;
    outr[q + 48] += z3;
    outr[q + 64] += z4;
}

// ---------------------------------------------------------------------------
extern "C" void kernel_launch(void* const* d_in, const int* in_sizes, int n_in,
                              void* d_out, int out_size) {
    const float* node_input   = (const float*)d_in[0];
    const float* node_attr    = (const float*)d_in[1];
    const float* edge_attr    = (const float*)d_in[2];
    const float* edge_scalars = (const float*)d_in[3];
    const float* Wsc0 = (const float*)d_in[4];
    const float* Wsc1 = (const float*)d_in[5];
    const float* Wl10 = (const float*)d_in[6];
    const float* Wl11 = (const float*)d_in[7];
    const float* Wfc0 = (const float*)d_in[8];
    const float* Wfc1 = (const float*)d_in[9];
    const float* Wl20 = (const float*)d_in[10];
    const float* Wl21 = (const float*)d_in[11];
    const int*   edge_index = (const int*)d_in[12];
    float* out = (float*)d_out;

    void* agg_ptr = nullptr;
    cudaGetSymbolAddress(&agg_ptr, g_agg);
    cudaMemsetAsync(agg_ptr, 0, (size_t)N_NODES * 192 * sizeof(float));

    node_kernel<<<(N_NODES + 15) / 16, 256>>>(node_input, node_attr,
                                              Wsc0, Wsc1, Wl10, Wl11, out);

    const int smem_bytes = (6784 + 12288) * 4;   // 76288 B
    cudaFuncSetAttribute(edge_kernel, cudaFuncAttributeMaxDynamicSharedMemorySize,
                         smem_bytes);
    edge_kernel<<<N_EDGES / MTILE, 256, smem_bytes>>>(edge_scalars, edge_attr,
                                                      edge_index, Wfc0, Wfc1);
    final_kernel<<<(N_NODES + 15) / 16, 256>>>(Wl20, Wl21, out);
}